// round 8
// baseline (speedup 1.0000x reference)
#include <cuda_runtime.h>
#include <cuda_fp16.h>
#include <math.h>
#include <stdint.h>

#define CIN   64
#define COUT  64
#define HH    112
#define WW    112
#define NB    32
#define HW    (HH*WW)            // 12544
#define TOTAL (NB*COUT*HW)       // 25690112
#define MCNT  (NB*HW)            // 401408

// conv tiling: block = 64 co x 256 px (16x16), 8 warps m32xn64, fp16 mma k16
// swizzled 128B rows: phys_chunk = logical_chunk ^ (row & 7)
#define TPX 16
#define TPY 16
#define NPOS (18*18)             // 324 halo positions
#define S_ACT_BYTES (NPOS*128)           // 41472
#define S_W_BYTES   (9*64*128)           // 73728 (all 9 taps resident)
#define SMEM_BYTES  (S_ACT_BYTES + S_W_BYTES)   // 115200 -> 2 CTAs/SM

// ---------------- device scratch ----------------
__device__ float  g_t1[TOTAL];
__device__ float  g_t2[TOTAL];
__device__ __half g_w1[9*64*64];   // [tap][co][swizzled chunk][ci&7]
__device__ __half g_w2[9*64*64];
__device__ float  g_sum[2][COUT];
__device__ float  g_sq[2][COUT];
__device__ float  g_scale[2][COUT];
__device__ float  g_bias[2][COUT];

__device__ __forceinline__ void mma16(float* d, const uint32_t* a, uint32_t b0, uint32_t b1) {
    asm volatile(
        "mma.sync.aligned.m16n8k16.row.col.f32.f16.f16.f32 "
        "{%0,%1,%2,%3}, {%4,%5,%6,%7}, {%8,%9}, {%0,%1,%2,%3};\n"
        : "+f"(d[0]), "+f"(d[1]), "+f"(d[2]), "+f"(d[3])
        : "r"(a[0]), "r"(a[1]), "r"(a[2]), "r"(a[3]), "r"(b0), "r"(b1));
}
__device__ __forceinline__ void ldsm4(uint32_t& r0, uint32_t& r1, uint32_t& r2, uint32_t& r3,
                                      uint32_t addr) {
    asm volatile("ldmatrix.sync.aligned.m8n8.x4.shared.b16 {%0,%1,%2,%3}, [%4];"
        : "=r"(r0), "=r"(r1), "=r"(r2), "=r"(r3) : "r"(addr));
}

// ---------------- prep: ternarize + repack into swizzled layout ----------------
__global__ void prep_kernel(const float* __restrict__ w1,
                            const float* __restrict__ w2) {
    int idx = blockIdx.x * 256 + threadIdx.x;
    if (idx < COUT) {
        g_sum[0][idx] = 0.f; g_sum[1][idx] = 0.f;
        g_sq[0][idx]  = 0.f; g_sq[1][idx]  = 0.f;
    }
    if (idx < 9*64*64) {
        // src OIHW: idx = (co*64 + ci)*9 + t
        int co = idx / (64*9);
        int ci = (idx / 9) & 63;
        int t  = idx % 9;
        int dst = t*4096 + co*64 + (((ci >> 3) ^ (co & 7)) << 3) + (ci & 7);
        float a = w1[idx];
        g_w1[dst] = __float2half((fabsf(a) > 0.3f) ? (a > 0.f ? 1.f : -1.f) : 0.f);
        float b = w2[idx];
        g_w2[dst] = __float2half((fabsf(b) > 0.3f) ? (b > 0.f ? 1.f : -1.f) : 0.f);
    }
}

// ---------------- conv3x3 via 9 shifted 1x1 GEMMs, fp16 mma + ldmatrix ----
// All 9 weight taps resident in swizzled smem: ONE barrier, then a 36-chunk
// uninterrupted LDSM/MMA stream.
// PASS 1: in=x, out=g_t1.  PASS 2: in=BN1+hardtanh(g_t1), out=g_t2 + x.
template<int PASS>
__global__ void __launch_bounds__(256, 2) conv_mma_kernel(const float* __restrict__ x) {
    extern __shared__ __half smem_h[];
    __half* s_act = smem_h;                               // [pos] 128B swizzled rows
    __half* s_w   = smem_h + S_ACT_BYTES/2;               // [tap][co] 128B swizzled rows
    __shared__ float s_s[COUT], s_b[COUT];
    __shared__ float s_sum[COUT], s_sq[COUT];

    const float*  in   = (PASS == 1) ? x    : g_t1;
    const __half* wrep = (PASS == 1) ? g_w1 : g_w2;
    float*        out  = (PASS == 1) ? g_t1 : g_t2;

    const int tid  = threadIdx.x;
    const int lane = tid & 31;
    const int wid  = tid >> 5;
    const int wm   = wid & 1;        // 2 m-tiles of 32 co
    const int wn   = wid >> 1;       // 4 n-tiles of 64 px
    const int q    = lane & 3;
    const int nidx = lane >> 2;
    const int w0   = blockIdx.x * TPX;
    const int h0   = blockIdx.y * TPY;
    const int n    = blockIdx.z;

    if (tid < COUT) {
        s_sum[tid] = 0.f; s_sq[tid] = 0.f;
        if (PASS == 2) { s_s[tid] = g_scale[0][tid]; s_b[tid] = g_bias[0][tid]; }
    }
    __syncthreads();   // s_s/s_b ready for PASS2 staging

    // ---- stage ALL weights: straight float4 copy (pre-swizzled in gmem) ----
    {
        const float4* src = reinterpret_cast<const float4*>(wrep);
        float4*       dst = reinterpret_cast<float4*>(s_w);
#pragma unroll
        for (int k = 0; k < 18; k++)
            dst[tid + k*256] = src[tid + k*256];
    }

    // ---- stage activation tile: 64 ci x 18x18 halo, fp16, swizzled rows ----
    // 8 consecutive lanes = 8 consecutive positions -> full 32B LDG sectors.
    {
        const int posg = tid & 7;
        const int ciw  = tid >> 3;       // 0..31
        const int ci   = 2*ciw;
        const int ck   = ci >> 3;        // logical chunk
        const float* p0 = in + (n*64 + ci)*HW;
        const float* p1 = p0 + HW;
        float sc0 = 0.f, bs0 = 0.f, sc1 = 0.f, bs1 = 0.f;
        if (PASS == 2) { sc0 = s_s[ci]; bs0 = s_b[ci]; sc1 = s_s[ci+1]; bs1 = s_b[ci+1]; }
        for (int pos = posg; pos < NPOS; pos += 8) {
            int py = pos / 18;
            int px = pos - py*18;
            int gh = h0 + py - 1, gw = w0 + px - 1;
            float v0 = 0.f, v1 = 0.f;
            if ((unsigned)gh < (unsigned)HH && (unsigned)gw < (unsigned)WW) {
                int o = gh*WW + gw;
                v0 = p0[o];
                v1 = p1[o];
                if (PASS == 2) {
                    v0 = fminf(fmaxf(fmaf(v0, sc0, bs0), -1.f), 1.f);
                    v1 = fminf(fmaxf(fmaf(v1, sc1, bs1), -1.f), 1.f);
                }
            }
            int adr = pos*64 + ((ck ^ (pos & 7)) << 3) + (ci & 7);   // half units
            *reinterpret_cast<__half2*>(s_act + adr) = __floats2half2_rn(v0, v1);
        }
    }

    float acc[2][8][4];
#pragma unroll
    for (int mt = 0; mt < 2; mt++)
#pragma unroll
        for (int nt = 0; nt < 8; nt++)
#pragma unroll
            for (int r = 0; r < 4; r++) acc[mt][nt][r] = 0.f;

    // ---- per-lane LDSM bases ----
    const uint32_t sa_b = (uint32_t)__cvta_generic_to_shared(s_act);
    const uint32_t sw_b = (uint32_t)__cvta_generic_to_shared(s_w);
    // A: lanes 0-15 rows co | lanes 16-31 same rows @k+8
    const int co_l    = wm*32 + (lane & 15);
    const uint32_t akofb = (uint32_t)(lane >> 4) * 16;
    // B: lanes 0-7 px0-7@k0 | 8-15 px0-7@k8 | 16-23 px8-15@k0 | 24-31 px8-15@k8
    const int px_l    = ((lane >> 4) & 1)*8 + (lane & 7);
    const uint32_t bkofb = (uint32_t)((lane >> 3) & 1) * 16;
    int pout[4];
#pragma unroll
    for (int pr = 0; pr < 4; pr++)
        pout[pr] = (wn*4 + pr)*18 + px_l;

    __syncthreads();   // act + weights staged

#pragma unroll
    for (int tap = 0; tap < 9; ++tap) {
        const int dy = tap / 3, dx = tap - dy*3;
        const int shift = dy*18 + dx;

        // A bases for this tap (rows = co, swizzle by co&7)
        uint32_t abase[2], aswz[2];
#pragma unroll
        for (int mt = 0; mt < 2; mt++) {
            int r = co_l + mt*16;
            abase[mt] = sw_b + (uint32_t)(tap*8192 + r*128);
            aswz[mt]  = (uint32_t)((r & 7) << 4);
        }
        // B bases for this tap (rows = shifted pos, swizzle by pos&7)
        uint32_t bbase[4], bswz[4];
#pragma unroll
        for (int pr = 0; pr < 4; pr++) {
            int pabs = pout[pr] + shift;
            bbase[pr] = sa_b + (uint32_t)(pabs << 7);
            bswz[pr]  = (uint32_t)((pabs & 7) << 4);
        }

#pragma unroll
        for (int ch = 0; ch < 4; ch++) {
            const uint32_t cb = (uint32_t)(ch*32);
            uint32_t a[2][4];
#pragma unroll
            for (int mt = 0; mt < 2; mt++)
                ldsm4(a[mt][0], a[mt][1], a[mt][2], a[mt][3],
                      abase[mt] + ((cb + akofb) ^ aswz[mt]));
#pragma unroll
            for (int pr = 0; pr < 4; pr++) {
                uint32_t b0, b1, b2, b3;
                ldsm4(b0, b1, b2, b3, bbase[pr] + ((cb + bkofb) ^ bswz[pr]));
                mma16(acc[0][2*pr],   a[0], b0, b1);
                mma16(acc[1][2*pr],   a[1], b0, b1);
                mma16(acc[0][2*pr+1], a[0], b2, b3);
                mma16(acc[1][2*pr+1], a[1], b2, b3);
            }
        }
    }

    // ---- epilogue: residual (+PASS2), store, fused BN stats ----
#pragma unroll
    for (int mt = 0; mt < 2; mt++) {
        int co_lo = wm*32 + mt*16 + nidx;
        float slo = 0.f, qlo = 0.f, shi = 0.f, qhi = 0.f;
#pragma unroll
        for (int nt = 0; nt < 8; nt++) {
            int p  = wn*64 + nt*8 + 2*q;
            int py = p >> 4, px = p & 15;
            int base = (n*64 + co_lo)*HW + (h0 + py)*WW + (w0 + px);
            float2 v0 = make_float2(acc[mt][nt][0], acc[mt][nt][1]);
            float2 v1 = make_float2(acc[mt][nt][2], acc[mt][nt][3]);
            if (PASS == 2) {
                float2 r0 = *(const float2*)(x + base);
                float2 r1 = *(const float2*)(x + base + 8*HW);
                v0.x += r0.x; v0.y += r0.y;
                v1.x += r1.x; v1.y += r1.y;
            }
            *(float2*)(out + base)        = v0;
            *(float2*)(out + base + 8*HW) = v1;
            slo += v0.x + v0.y;
            qlo += v0.x*v0.x + v0.y*v0.y;
            shi += v1.x + v1.y;
            qhi += v1.x*v1.x + v1.y*v1.y;
        }
#pragma unroll
        for (int o = 1; o <= 2; o <<= 1) {
            slo += __shfl_xor_sync(0xffffffffu, slo, o);
            qlo += __shfl_xor_sync(0xffffffffu, qlo, o);
            shi += __shfl_xor_sync(0xffffffffu, shi, o);
            qhi += __shfl_xor_sync(0xffffffffu, qhi, o);
        }
        if (q == 0) {
            atomicAdd(&s_sum[co_lo],     slo);
            atomicAdd(&s_sq[co_lo],      qlo);
            atomicAdd(&s_sum[co_lo + 8], shi);
            atomicAdd(&s_sq[co_lo + 8],  qhi);
        }
    }
    __syncthreads();
    if (tid < COUT) {
        atomicAdd(&g_sum[PASS-1][tid], s_sum[tid]);
        atomicAdd(&g_sq[PASS-1][tid],  s_sq[tid]);
    }
}

// ---------------- fold BN stats ----------------
template<int PASS>
__global__ void finalize_kernel(const float* __restrict__ g,
                                const float* __restrict__ b) {
    int c = threadIdx.x;
    if (c < COUT) {
        const float inv = 1.f / (float)MCNT;
        float mean = g_sum[PASS-1][c] * inv;
        float var  = g_sq[PASS-1][c] * inv - mean*mean;
        float s    = g[c] * rsqrtf(var + 1e-5f);
        g_scale[PASS-1][c] = s;
        g_bias[PASS-1][c]  = b[c] - mean*s;
    }
}

// ---------------- final BN2 + hardtanh ----------------
__global__ void bnact_kernel(float* __restrict__ out) {
    int i = blockIdx.x * 256 + threadIdx.x;
    if (i >= TOTAL/4) return;
    int c = (i / (HW/4)) & 63;
    float s  = g_scale[1][c];
    float bb = g_bias[1][c];
    float4 v = reinterpret_cast<const float4*>(g_t2)[i];
    v.x = fminf(fmaxf(fmaf(v.x, s, bb), -1.f), 1.f);
    v.y = fminf(fmaxf(fmaf(v.y, s, bb), -1.f), 1.f);
    v.z = fminf(fmaxf(fmaf(v.z, s, bb), -1.f), 1.f);
    v.w = fminf(fmaxf(fmaf(v.w, s, bb), -1.f), 1.f);
    reinterpret_cast<float4*>(out)[i] = v;
}

// ---------------- launch ----------------
extern "C" void kernel_launch(void* const* d_in, const int* in_sizes, int n_in,
                              void* d_out, int out_size) {
    const float* x  = (const float*)d_in[0];
    const float* w1 = (const float*)d_in[1];
    const float* g1 = (const float*)d_in[2];
    const float* b1 = (const float*)d_in[3];
    const float* w2 = (const float*)d_in[4];
    const float* g2 = (const float*)d_in[5];
    const float* b2 = (const float*)d_in[6];
    float* out = (float*)d_out;

    cudaFuncSetAttribute(conv_mma_kernel<1>,
                         cudaFuncAttributeMaxDynamicSharedMemorySize, SMEM_BYTES);
    cudaFuncSetAttribute(conv_mma_kernel<2>,
                         cudaFuncAttributeMaxDynamicSharedMemorySize, SMEM_BYTES);

    prep_kernel<<<(9*64*64 + 255)/256, 256>>>(w1, w2);

    dim3 cgrid(WW/TPX, HH/TPY, NB);   // (7, 7, 32)
    conv_mma_kernel<1><<<cgrid, 256, SMEM_BYTES>>>(x);
    finalize_kernel<1><<<1, 64>>>(g1, b1);

    conv_mma_kernel<2><<<cgrid, 256, SMEM_BYTES>>>(x);
    finalize_kernel<2><<<1, 64>>>(g2, b2);

    bnact_kernel<<<(TOTAL/4 + 255)/256, 256>>>(out);
}